// round 11
// baseline (speedup 1.0000x reference)
#include <cuda_runtime.h>
#include <cstdint>

// out[b,t,c] = sum_s exp(-4*(sw[b,t] + s - t)^2) * input[b,s,c]
// WIDTH=0.25 -> 3-tap window {r-1, r, r+1}, r = round(t - sw); dropped taps
// weigh <= exp(-9) = 1.23e-4 vs kept sum >= 0.74 -> rel err ~3e-4 worst case
// (threshold 1e-3; measured 4.5e-5). 2-tap rejected: ~4e-3 > threshold.
//
// Round-11 composite of the best-measured pieces across rounds 1-10:
//  - round-4 shape (best bench, 8.70us): 4 t per warp, two halves of 2 t
//    (6 LDG.128 in flight), 256-thr blocks, grid (64,16)=1024
//  - round-9 lean math (exp2 factorization, base-pointer + immediate-offset
//    taps) but weights computed PER HALF so only r[4], f[4] stay live ->
//    ~32-36 regs instead of round-9's 44, restoring round-4 occupancy
//  - float4 sw broadcast, st.global.cs output stores (keep input L2-resident)
// Cross-round evidence says warm-L2 bench floor ~8.7us is mostly external
// (replay overhead + write drain + 2-hop L2 latency); this kernel ties the
// best shape at the lowest register/instruction cost.

#define S_DIM 4096
#define T_DIM 2048
#define C_DIM 128
#define C4    (C_DIM / 4)

__device__ __forceinline__ float ex2(float x) {
    float y;
    asm("ex2.approx.f32 %0, %1;" : "=f"(y) : "f"(x));
    return y;
}

__device__ __forceinline__ void st_cs_v4(float4* p, float4 v) {
    asm volatile("st.global.cs.v4.f32 [%0], {%1, %2, %3, %4};"
                 :: "l"(p), "f"(v.x), "f"(v.y), "f"(v.z), "f"(v.w));
}

__global__ __launch_bounds__(256)
void shifting_window_kernel(const float* __restrict__ inp,
                            const float* __restrict__ sw,
                            float* __restrict__ out) {
    const int b    = blockIdx.y;
    const int warp = threadIdx.x >> 5;                 // 0..7
    const int lane = threadIdx.x & 31;
    const int t0   = (blockIdx.x << 5) + (warp << 2);  // 4 t per warp

    const float4* __restrict__ row =
        (const float4*)(inp + (size_t)b * S_DIM * C_DIM);

    // sw[t0..t0+3] in one broadcast float4 (t0 % 4 == 0, 16B aligned).
    const float4 swv = *(const float4*)(sw + b * T_DIM + t0);
    const float wv[4] = {swv.x, swv.y, swv.z, swv.w};

    int   r[4];
    float f[4];                                        // frac in [-0.5, 0.5]
#pragma unroll
    for (int j = 0; j < 4; ++j) {
        r[j] = __float2int_rn((float)(t0 + j) - wv[j]);
        f[j] = wv[j] + (float)(r[j] - (t0 + j));
    }

    if (t0 >= 8) {
        // Hot path: s in [t-6, t+6] subset of [2, 2054) -> no bounds checks.
#pragma unroll
        for (int half = 0; half < 2; ++half) {
            const int j0 = half << 1;
            float4 acc[2];
#pragma unroll
            for (int jj = 0; jj < 2; ++jj) {
                const int j = j0 + jj;
                // Weights recomputed per half: transient registers only.
                const float A  = -5.770780f * f[j] * f[j];   // -4 f^2 log2(e)
                const float u  = 11.541560f * f[j];          //  8 f   log2(e)
                const float w0 = ex2(A);
                const float wm = ex2(A + u - 5.770780f);     // tap r-1
                const float wp = ex2(A - u - 5.770780f);     // tap r+1
                // Base pointer at tap r-1; taps at +0 / +512B / +1024B.
                const float4* p = &row[(r[j] - 1) * C4 + lane];
                const float4 vm = p[0];
                const float4 v0 = p[C4];
                const float4 vp = p[2 * C4];
                float4 a;
                a.x = wm * vm.x; a.y = wm * vm.y;
                a.z = wm * vm.z; a.w = wm * vm.w;
                a.x = fmaf(w0, v0.x, a.x); a.y = fmaf(w0, v0.y, a.y);
                a.z = fmaf(w0, v0.z, a.z); a.w = fmaf(w0, v0.w, a.w);
                a.x = fmaf(wp, vp.x, a.x); a.y = fmaf(wp, vp.y, a.y);
                a.z = fmaf(wp, vp.z, a.z); a.w = fmaf(wp, vp.w, a.w);
                acc[jj] = a;
            }
#pragma unroll
            for (int jj = 0; jj < 2; ++jj) {
                float4* o = (float4*)(out +
                    ((size_t)b * T_DIM + (t0 + j0 + jj)) * C_DIM);
                st_cs_v4(o + lane, acc[jj]);
            }
        }
    } else {
        // Cold path (2 warps in the whole grid): clamp address, zero weight.
#pragma unroll
        for (int j = 0; j < 4; ++j) {
            const float A  = -5.770780f * f[j] * f[j];
            const float u  = 11.541560f * f[j];
            const float w3[3] = {ex2(A + u - 5.770780f),
                                 ex2(A),
                                 ex2(A - u - 5.770780f)};
            float4 acc = make_float4(0.f, 0.f, 0.f, 0.f);
#pragma unroll
            for (int i = -1; i <= 1; ++i) {
                const int s    = r[j] + i;
                float     wgt  = w3[i + 1];
                if (s < 0) wgt = 0.f;
                const int s_ld = (s < 0) ? 0 : s;
                const float4 v = row[s_ld * C4 + lane];
                acc.x = fmaf(wgt, v.x, acc.x);
                acc.y = fmaf(wgt, v.y, acc.y);
                acc.z = fmaf(wgt, v.z, acc.z);
                acc.w = fmaf(wgt, v.w, acc.w);
            }
            float4* o = (float4*)(out + ((size_t)b * T_DIM + (t0 + j)) * C_DIM);
            st_cs_v4(o + lane, acc);
        }
    }
}

extern "C" void kernel_launch(void* const* d_in, const int* in_sizes, int n_in,
                              void* d_out, int out_size) {
    const float* inp = (const float*)d_in[0];   // (B, S, C) fp32
    const float* sw  = (const float*)d_in[1];   // (B, T)   fp32
    float* out       = (float*)d_out;           // (B, T, C) fp32

    dim3 grid(T_DIM / 32, 16, 1);   // (64, 16) = 1024 blocks
    dim3 block(256, 1, 1);
    shifting_window_kernel<<<grid, block>>>(inp, sw, out);
}

// round 12
// speedup vs baseline: 1.0812x; 1.0812x over previous
#include <cuda_runtime.h>

// out[b,t,c] = sum_s exp(-4*(sw[b,t] + s - t)^2) * input[b,s,c]
// WIDTH=0.25 -> weight = exp(-4 d^2). Window = 3 taps {r-1, r, r+1} around
// r = round(t - sw): nearest dropped tap has |d| >= 1.5 -> weight <= 1.23e-4
// vs kept-weight sum >= 0.74 -> rel err ~2e-4 worst case (threshold 1e-3).
//
// B=16, S=4096, T=2048, C=128.
// FINAL: this is the round-4 kernel verbatim — the best-measured
// configuration (8.70us) across a 10-round structural search (occupancy
// 37-75%, grids 512-2048, 1-4 t/warp, MLP 3-12, smem band staging, cp.async
// pipelining, -40% instruction count, streaming stores: all neutral or
// worse). The bench floor is external to the kernel at this formulation:
// mandatory 16.8MB output drain + warm-L2 gather pipeline + replay overhead.
//
// 1 warp owns 4 consecutive t, processed as TWO halves of 2 t each so only
// 6 float4 loads are in flight at once (24 regs) instead of 12 (48 regs).
// Block = 256 thr = 8 warps = 32 t. Grid = (T/32, B) = (64, 16) = 1024.

#define S_DIM 4096
#define T_DIM 2048
#define C_DIM 128

__global__ __launch_bounds__(256, 7)
void shifting_window_kernel(const float* __restrict__ inp,
                            const float* __restrict__ sw,
                            float* __restrict__ out) {
    const int b    = blockIdx.y;
    const int warp = threadIdx.x >> 5;                 // 0..7
    const int lane = threadIdx.x & 31;
    const int t0   = (blockIdx.x << 5) + (warp << 2);  // 4 t per warp

    const float4* __restrict__ row =
        (const float4*)(inp + (size_t)b * S_DIM * C_DIM);

    if (t0 >= 8) {
        // Hot path: no bounds checks (|sw| ~<= 4.5 -> s in [2, 2054) always).
#pragma unroll
        for (int half = 0; half < 2; ++half) {
            const int tb = t0 + (half << 1);
            float  w[2];
            int    r[2];
            float4 acc[2];
#pragma unroll
            for (int j = 0; j < 2; ++j) {
                const int t = tb + j;
                w[j] = sw[b * T_DIM + t];
                r[j] = __float2int_rn((float)t - w[j]);
                acc[j] = make_float4(0.f, 0.f, 0.f, 0.f);
            }
#pragma unroll
            for (int i = -1; i <= 1; ++i) {
#pragma unroll
                for (int j = 0; j < 2; ++j) {
                    const int   s   = r[j] + i;
                    const float d   = w[j] + (float)(s - (tb + j));
                    const float wgt = __expf(-4.0f * d * d);
                    const float4 v  = row[s * (C_DIM / 4) + lane];
                    acc[j].x = fmaf(wgt, v.x, acc[j].x);
                    acc[j].y = fmaf(wgt, v.y, acc[j].y);
                    acc[j].z = fmaf(wgt, v.z, acc[j].z);
                    acc[j].w = fmaf(wgt, v.w, acc[j].w);
                }
            }
#pragma unroll
            for (int j = 0; j < 2; ++j) {
                float4* __restrict__ o =
                    (float4*)(out + ((size_t)b * T_DIM + (tb + j)) * C_DIM);
                o[lane] = acc[j];
            }
        }
    } else {
        // Cold path (2 warps total across the grid): guard s >= 0.
#pragma unroll
        for (int half = 0; half < 2; ++half) {
            const int tb = t0 + (half << 1);
            float  w[2];
            int    r[2];
            float4 acc[2];
#pragma unroll
            for (int j = 0; j < 2; ++j) {
                const int t = tb + j;
                w[j] = sw[b * T_DIM + t];
                r[j] = __float2int_rn((float)t - w[j]);
                acc[j] = make_float4(0.f, 0.f, 0.f, 0.f);
            }
#pragma unroll
            for (int i = -1; i <= 1; ++i) {
#pragma unroll
                for (int j = 0; j < 2; ++j) {
                    const int   s   = r[j] + i;
                    const float d   = w[j] + (float)(s - (tb + j));
                    const float wgt = __expf(-4.0f * d * d);
                    if (s >= 0) {
                        const float4 v = row[s * (C_DIM / 4) + lane];
                        acc[j].x = fmaf(wgt, v.x, acc[j].x);
                        acc[j].y = fmaf(wgt, v.y, acc[j].y);
                        acc[j].z = fmaf(wgt, v.z, acc[j].z);
                        acc[j].w = fmaf(wgt, v.w, acc[j].w);
                    }
                }
            }
#pragma unroll
            for (int j = 0; j < 2; ++j) {
                float4* __restrict__ o =
                    (float4*)(out + ((size_t)b * T_DIM + (tb + j)) * C_DIM);
                o[lane] = acc[j];
            }
        }
    }
}

extern "C" void kernel_launch(void* const* d_in, const int* in_sizes, int n_in,
                              void* d_out, int out_size) {
    const float* inp = (const float*)d_in[0];   // (B, S, C) fp32
    const float* sw  = (const float*)d_in[1];   // (B, T)   fp32
    float* out       = (float*)d_out;           // (B, T, C) fp32

    dim3 grid(T_DIM / 32, 16, 1);   // 32 t per block, B = 16 -> 1024 blocks
    dim3 block(256, 1, 1);
    shifting_window_kernel<<<grid, block>>>(inp, sw, out);
}